// round 1
// baseline (speedup 1.0000x reference)
#include <cuda_runtime.h>
#include <math.h>

#define B   16
#define IN  1024
#define HH  1024
#define DKK 1024
#define D1  4096
#define LRC 0.01f
#define NCH 16
#define CI  (HH / NCH)   // 64 rows of W1 per partial chunk

// ---------------- scratch (allocation-free) ----------------
__device__ __align__(16) float g_K[B * DKK];
__device__ __align__(16) float g_V[B * HH];
__device__ __align__(16) float g_G[B * D1];
__device__ __align__(16) float g_Gp[B * D1];
__device__ __align__(16) float g_Hd[B * HH];
__device__ __align__(16) float g_dH[B * HH];
__device__ __align__(16) float g_dZ[B * D1];
__device__ __align__(16) float g_part[NCH * B * D1];  // 4 MB

__device__ __forceinline__ float warp_sum(float v) {
    v += __shfl_xor_sync(0xffffffffu, v, 16);
    v += __shfl_xor_sync(0xffffffffu, v, 8);
    v += __shfl_xor_sync(0xffffffffu, v, 4);
    v += __shfl_xor_sync(0xffffffffu, v, 2);
    v += __shfl_xor_sync(0xffffffffu, v, 1);
    return v;
}

// ---------------- K = X @ Wk^T, V = X @ Wv^T ----------------
// one warp per (matrix, row j); 16 batch accumulators per lane
__global__ void proj_kernel(const float* __restrict__ X,
                            const float* __restrict__ Wk,
                            const float* __restrict__ Wv) {
    int warp = (blockIdx.x * blockDim.x + threadIdx.x) >> 5;
    int lane = threadIdx.x & 31;
    int m = warp >> 10;            // 0 -> K, 1 -> V
    int j = warp & 1023;
    const float* W = m ? Wv : Wk;
    float* out = m ? g_V : g_K;
    const float* wrow = W + (size_t)j * IN;

    float acc[B];
#pragma unroll
    for (int b = 0; b < B; b++) acc[b] = 0.f;

    for (int i = lane; i < IN; i += 32) {
        float w = __ldg(wrow + i);
#pragma unroll
        for (int b = 0; b < B; b++) acc[b] += w * __ldg(X + b * IN + i);
    }
#pragma unroll
    for (int b = 0; b < B; b++) acc[b] = warp_sum(acc[b]);
    if (lane == 0) {
#pragma unroll
        for (int b = 0; b < B; b++) out[b * 1024 + j] = acc[b];
    }
}

// ---------------- Z = K @ W0^T ; G = gelu(Z), Gp = gelu'(Z) ----------------
__global__ void zgelu_kernel(const float* __restrict__ W0) {
    int warp = (blockIdx.x * blockDim.x + threadIdx.x) >> 5;  // j in [0,4096)
    int lane = threadIdx.x & 31;
    const float* wrow = W0 + (size_t)warp * DKK;

    float acc[B];
#pragma unroll
    for (int b = 0; b < B; b++) acc[b] = 0.f;

    for (int i = lane; i < DKK; i += 32) {
        float w = __ldg(wrow + i);
#pragma unroll
        for (int b = 0; b < B; b++) acc[b] += w * g_K[b * DKK + i];
    }
#pragma unroll
    for (int b = 0; b < B; b++) acc[b] = warp_sum(acc[b]);
    if (lane == 0) {
#pragma unroll
        for (int b = 0; b < B; b++) {
            float z  = acc[b];
            float c  = 0.5f * (1.f + erff(z * 0.70710678118654752f));
            float g  = z * c;
            float gp = c + z * 0.39894228040143268f * expf(-0.5f * z * z);
            g_G [b * D1 + warp] = g;
            g_Gp[b * D1 + warp] = gp;
        }
    }
}

// ---------------- Hd = G @ W1^T ; dH = (Hd - V)/H ----------------
__global__ void hdh_kernel(const float* __restrict__ W1) {
    int warp = (blockIdx.x * blockDim.x + threadIdx.x) >> 5;  // i in [0,1024)
    int lane = threadIdx.x & 31;
    const float* wrow = W1 + (size_t)warp * D1;

    float acc[B];
#pragma unroll
    for (int b = 0; b < B; b++) acc[b] = 0.f;

    for (int j = lane; j < D1; j += 32) {
        float w = __ldg(wrow + j);
#pragma unroll
        for (int b = 0; b < B; b++) acc[b] += w * g_G[b * D1 + j];
    }
#pragma unroll
    for (int b = 0; b < B; b++) acc[b] = warp_sum(acc[b]);
    if (lane == 0) {
#pragma unroll
        for (int b = 0; b < B; b++) {
            float h = acc[b];
            g_Hd[b * HH + warp] = h;
            g_dH[b * HH + warp] = (h - g_V[b * HH + warp]) * (1.0f / (float)HH);
        }
    }
}

// ---------------- partial dG: part[c][b][j] = sum_{i in chunk c} dH[b,i]*W1[i,j] ----------------
// deterministic (no atomics); column-coalesced W1 reads
__global__ void dgpart_kernel(const float* __restrict__ W1) {
    int j = blockIdx.x * blockDim.x + threadIdx.x;  // 0..4095
    int c = blockIdx.y;                             // chunk
    float acc[B];
#pragma unroll
    for (int b = 0; b < B; b++) acc[b] = 0.f;

    int i0 = c * CI;
    for (int r = 0; r < CI; r++) {
        int i = i0 + r;
        float w = __ldg(W1 + (size_t)i * D1 + j);
#pragma unroll
        for (int b = 0; b < B; b++) acc[b] += g_dH[b * HH + i] * w;
    }
#pragma unroll
    for (int b = 0; b < B; b++) g_part[(c * B + b) * D1 + j] = acc[b];
}

// ---------------- dZ = (sum_c part) * Gp ----------------
__global__ void dz_kernel() {
    int t = blockIdx.x * blockDim.x + threadIdx.x;  // 0..B*D1-1
    int b = t / D1;
    int j = t % D1;
    float s = 0.f;
#pragma unroll
    for (int c = 0; c < NCH; c++) s += g_part[(c * B + b) * D1 + j];
    g_dZ[b * D1 + j] = s * g_Gp[b * D1 + j];
}

// ---------------- output = Hd @ Wo^T ----------------
__global__ void out_kernel(const float* __restrict__ Wo, float* __restrict__ out) {
    int warp = (blockIdx.x * blockDim.x + threadIdx.x) >> 5;  // n in [0,1024)
    int lane = threadIdx.x & 31;
    const float* wrow = Wo + (size_t)warp * HH;

    float acc[B];
#pragma unroll
    for (int b = 0; b < B; b++) acc[b] = 0.f;

    for (int h = lane; h < HH; h += 32) {
        float w = __ldg(wrow + h);
#pragma unroll
        for (int b = 0; b < B; b++) acc[b] += w * g_Hd[b * HH + h];
    }
#pragma unroll
    for (int b = 0; b < B; b++) acc[b] = warp_sum(acc[b]);
    if (lane == 0) {
#pragma unroll
        for (int b = 0; b < B; b++) out[b * IN + warp] = acc[b];
    }
}

// ---------------- W0_new[b] = W0 - LR * dZ[b] (x) K[b] ----------------
// grid (1, 512, 16), 256 thr; each block: 8 d1-rows, full 1024 dk via float4
__global__ void updw0_kernel(const float* __restrict__ W0, float* __restrict__ out) {
    int b  = blockIdx.z;
    int dk = threadIdx.x * 4;
    float4 kk = *reinterpret_cast<const float4*>(g_K + b * DKK + dk);
    int d1base = blockIdx.y * 8;
#pragma unroll
    for (int r = 0; r < 8; r++) {
        int d1 = d1base + r;
        float s = LRC * g_dZ[b * D1 + d1];
        float4 w = __ldg(reinterpret_cast<const float4*>(W0 + (size_t)d1 * DKK + dk));
        float4 o;
        o.x = w.x - s * kk.x;
        o.y = w.y - s * kk.y;
        o.z = w.z - s * kk.z;
        o.w = w.w - s * kk.w;
        __stcs(reinterpret_cast<float4*>(out + ((size_t)b * D1 + d1) * DKK + dk), o);
    }
}

// ---------------- W1_new[b] = W1 - LR * dH[b] (x) G[b] ----------------
// grid (4, 128, 16), 256 thr; each block: 8 h-rows, 1024 of 4096 d via float4
__global__ void updw1_kernel(const float* __restrict__ W1, float* __restrict__ out) {
    int b = blockIdx.z;
    int d = blockIdx.x * 1024 + threadIdx.x * 4;
    float4 gg = *reinterpret_cast<const float4*>(g_G + b * D1 + d);
    int hbase = blockIdx.y * 8;
#pragma unroll
    for (int r = 0; r < 8; r++) {
        int h = hbase + r;
        float s = LRC * g_dH[b * HH + h];
        float4 w = __ldg(reinterpret_cast<const float4*>(W1 + (size_t)h * D1 + d));
        float4 o;
        o.x = w.x - s * gg.x;
        o.y = w.y - s * gg.y;
        o.z = w.z - s * gg.z;
        o.w = w.w - s * gg.w;
        __stcs(reinterpret_cast<float4*>(out + ((size_t)b * HH + h) * D1 + d), o);
    }
}

extern "C" void kernel_launch(void* const* d_in, const int* in_sizes, int n_in,
                              void* d_out, int out_size) {
    const float* x  = (const float*)d_in[0];  // [16,1024]
    const float* Wk = (const float*)d_in[1];  // [1024,1024]
    const float* Wv = (const float*)d_in[2];  // [1024,1024]
    const float* Wo = (const float*)d_in[3];  // [1024,1024]
    const float* W0 = (const float*)d_in[4];  // [4096,1024]
    const float* W1 = (const float*)d_in[5];  // [1024,4096]

    float* out      = (float*)d_out;                                   // output [16,1024]
    float* out_w0   = out + (size_t)B * IN;                            // W0_new [16,4096,1024]
    float* out_w1   = out_w0 + (size_t)B * D1 * DKK;                   // W1_new [16,1024,4096]

    proj_kernel <<<256, 256>>>(x, Wk, Wv);             // 2048 warps
    zgelu_kernel<<<512, 256>>>(W0);                    // 4096 warps
    hdh_kernel  <<<128, 256>>>(W1);                    // 1024 warps
    dgpart_kernel<<<dim3(D1 / 256, NCH, 1), 256>>>(W1);
    dz_kernel   <<<(B * D1) / 256, 256>>>();
    out_kernel  <<<128, 256>>>(Wo, out);
    updw0_kernel<<<dim3(1, D1 / 8, B), 256>>>(W0, out_w0);
    updw1_kernel<<<dim3(D1 / 1024, HH / 8, B), 256>>>(W1, out_w1);
}

// round 2
// speedup vs baseline: 2.5039x; 2.5039x over previous
#include <cuda_runtime.h>
#include <math.h>

#define B    16
#define IN   1024
#define HH   1024
#define DKK  1024
#define D1   4096
#define LRC  0.01f
#define NCH  32
#define CI   32              // rows of W1 per dG chunk

// ---------------- scratch (allocation-free) ----------------
__device__ __align__(16) float g_K  [B * DKK];        // b-major
__device__ __align__(16) float g_V  [B * HH];         // b-major
__device__ __align__(16) float g_G  [B * D1];         // b-major
__device__ __align__(16) float g_Gp [B * D1];         // b-major
__device__ __align__(16) float g_Hd [B * HH];         // b-major
__device__ __align__(16) float g_dHt[HH * B];         // i-major (x16 b)
__device__ __align__(16) float g_dZ [B * D1];         // b-major
__device__ __align__(16) float g_part[NCH * B * D1];  // 8 MB partials

__device__ __forceinline__ float warp_sum(float v) {
    v += __shfl_xor_sync(0xffffffffu, v, 16);
    v += __shfl_xor_sync(0xffffffffu, v, 8);
    v += __shfl_xor_sync(0xffffffffu, v, 4);
    v += __shfl_xor_sync(0xffffffffu, v, 2);
    v += __shfl_xor_sync(0xffffffffu, v, 1);
    return v;
}
__device__ __forceinline__ float dot4(float4 a, float4 b) {
    return a.x * b.x + a.y * b.y + a.z * b.z + a.w * b.w;
}

// ---------------- K = X @ Wk^T, V = X @ Wv^T (warp per (m,j)) ----------------
__global__ void proj_kernel(const float* __restrict__ X,
                            const float* __restrict__ Wk,
                            const float* __restrict__ Wv) {
    int gw   = (blockIdx.x * blockDim.x + threadIdx.x) >> 5;
    int lane = threadIdx.x & 31;
    int m = gw >> 10;
    int j = gw & 1023;
    const float* wrow = (m ? Wv : Wk) + (size_t)j * IN;

    float acc[B];
#pragma unroll
    for (int b = 0; b < B; b++) acc[b] = 0.f;

#pragma unroll 2
    for (int it = 0; it < 8; it++) {
        int i0 = it * 128 + lane * 4;
        float4 w4 = __ldg((const float4*)(wrow + i0));
#pragma unroll
        for (int b = 0; b < B; b++) {
            float4 x4 = __ldg((const float4*)(X + b * IN + i0));
            acc[b] += dot4(w4, x4);
        }
    }
#pragma unroll
    for (int b = 0; b < B; b++) acc[b] = warp_sum(acc[b]);
    if (lane == 0) {
        float* out = m ? g_V : g_K;
#pragma unroll
        for (int b = 0; b < B; b++) out[b * 1024 + j] = acc[b];
    }
}

// ---------------- Z = K @ W0^T ; G = gelu(Z), Gp = gelu'(Z) (warp per j) ----------------
__global__ void zgelu_kernel(const float* __restrict__ W0) {
    int j    = (blockIdx.x * blockDim.x + threadIdx.x) >> 5;
    int lane = threadIdx.x & 31;
    const float* wrow = W0 + (size_t)j * DKK;

    float acc[B];
#pragma unroll
    for (int b = 0; b < B; b++) acc[b] = 0.f;

#pragma unroll 2
    for (int it = 0; it < 8; it++) {
        int i0 = it * 128 + lane * 4;
        float4 w4 = __ldg((const float4*)(wrow + i0));
#pragma unroll
        for (int b = 0; b < B; b++) {
            float4 k4 = *(const float4*)(g_K + b * DKK + i0);
            acc[b] += dot4(w4, k4);
        }
    }
#pragma unroll
    for (int b = 0; b < B; b++) acc[b] = warp_sum(acc[b]);
    if (lane == 0) {
#pragma unroll
        for (int b = 0; b < B; b++) {
            float z  = acc[b];
            float c  = 0.5f * (1.f + erff(z * 0.70710678118654752f));
            float g  = z * c;
            float gp = c + z * 0.39894228040143268f * expf(-0.5f * z * z);
            g_G [b * D1 + j] = g;
            g_Gp[b * D1 + j] = gp;
        }
    }
}

// ---------------- Hd = G @ W1^T ; dH = (Hd - V)/H (split-4, 2 rows/block) ----------------
__global__ void hdh_kernel(const float* __restrict__ W1) {
    __shared__ float sm[2][4][B];
    int w    = threadIdx.x >> 5;
    int lane = threadIdx.x & 31;
    int r = w >> 2;
    int s = w & 3;
    int i = blockIdx.x * 2 + r;
    const float* wrow = W1 + (size_t)i * D1 + s * 1024;

    float acc[B];
#pragma unroll
    for (int b = 0; b < B; b++) acc[b] = 0.f;

#pragma unroll 2
    for (int it = 0; it < 8; it++) {
        int j0 = it * 128 + lane * 4;
        float4 w4 = __ldg((const float4*)(wrow + j0));
#pragma unroll
        for (int b = 0; b < B; b++) {
            float4 g4 = *(const float4*)(g_G + b * D1 + s * 1024 + j0);
            acc[b] += dot4(w4, g4);
        }
    }
#pragma unroll
    for (int b = 0; b < B; b++) acc[b] = warp_sum(acc[b]);
    if (lane == 0) {
#pragma unroll
        for (int b = 0; b < B; b++) sm[r][s][b] = acc[b];
    }
    __syncthreads();
    if (threadIdx.x < 32) {
        int rr = threadIdx.x >> 4;
        int b  = threadIdx.x & 15;
        int ii = blockIdx.x * 2 + rr;
        float h = sm[rr][0][b] + sm[rr][1][b] + sm[rr][2][b] + sm[rr][3][b];
        g_Hd [b * HH + ii]  = h;
        g_dHt[ii * B + b]   = (h - g_V[b * HH + ii]) * (1.0f / (float)HH);
    }
}

// ---------------- partial dG: part[c][b][j] = sum_{i in chunk} dH[b,i]*W1[i,j] ----------------
__global__ void dgpart_kernel(const float* __restrict__ W1) {
    __shared__ float sdh[CI * B];
    int tid = threadIdx.x;
    int j   = blockIdx.x * 256 + tid;
    int c   = blockIdx.y;
    int i0  = c * CI;
    sdh[tid]       = g_dHt[i0 * B + tid];
    sdh[tid + 256] = g_dHt[i0 * B + tid + 256];
    __syncthreads();

    float acc[B];
#pragma unroll
    for (int b = 0; b < B; b++) acc[b] = 0.f;

#pragma unroll 4
    for (int r = 0; r < CI; r++) {
        float wv = __ldg(W1 + (size_t)(i0 + r) * D1 + j);
#pragma unroll
        for (int b = 0; b < B; b++) acc[b] += sdh[r * B + b] * wv;
    }
#pragma unroll
    for (int b = 0; b < B; b++) g_part[((size_t)c * B + b) * D1 + j] = acc[b];
}

// ---------------- dZ = (sum_c part) * Gp ----------------
__global__ void dz_kernel() {
    int t = blockIdx.x * blockDim.x + threadIdx.x;
    int b = t >> 12;
    int j = t & 4095;
    float s = 0.f;
#pragma unroll
    for (int c = 0; c < NCH; c++) s += g_part[((size_t)c * B + b) * D1 + j];
    g_dZ[b * D1 + j] = s * g_Gp[b * D1 + j];
}

// ---------------- output = Hd @ Wo^T (split-2, 4 rows/block) ----------------
__global__ void out_kernel(const float* __restrict__ Wo, float* __restrict__ out) {
    __shared__ float sm[4][2][B];
    int w    = threadIdx.x >> 5;
    int lane = threadIdx.x & 31;
    int r = w >> 1;
    int s = w & 1;
    int n = blockIdx.x * 4 + r;
    const float* wrow = Wo + (size_t)n * HH + s * 512;

    float acc[B];
#pragma unroll
    for (int b = 0; b < B; b++) acc[b] = 0.f;

#pragma unroll 2
    for (int it = 0; it < 4; it++) {
        int h0 = it * 128 + lane * 4;
        float4 w4 = __ldg((const float4*)(wrow + h0));
#pragma unroll
        for (int b = 0; b < B; b++) {
            float4 h4 = *(const float4*)(g_Hd + b * HH + s * 512 + h0);
            acc[b] += dot4(w4, h4);
        }
    }
#pragma unroll
    for (int b = 0; b < B; b++) acc[b] = warp_sum(acc[b]);
    if (lane == 0) {
#pragma unroll
        for (int b = 0; b < B; b++) sm[r][s][b] = acc[b];
    }
    __syncthreads();
    if (threadIdx.x < 64) {
        int rr = threadIdx.x >> 4;
        int b  = threadIdx.x & 15;
        int nn = blockIdx.x * 4 + rr;
        out[b * IN + nn] = sm[rr][0][b] + sm[rr][1][b];
    }
}

// ---------------- fused updates: each block = one 1024-float row segment, all 16 b ----------------
// W element read from DRAM exactly once; 16 streaming float4 stores per thread.
__global__ void update_kernel(const float* __restrict__ W0,
                              const float* __restrict__ W1,
                              float* __restrict__ out_w0,
                              float* __restrict__ out_w1) {
    int bx  = blockIdx.x;
    int col = threadIdx.x * 4;

    if (bx < 4096) {
        int d1 = bx;
        float s[B];
#pragma unroll
        for (int b = 0; b < B; b++) s[b] = LRC * g_dZ[b * D1 + d1];
        float4 w4 = __ldg((const float4*)(W0 + (size_t)d1 * DKK + col));
        float* dst = out_w0 + (size_t)d1 * DKK + col;
#pragma unroll 4
        for (int b = 0; b < B; b++) {
            float4 a4 = *(const float4*)(g_K + b * DKK + col);
            float4 o;
            o.x = w4.x - s[b] * a4.x;
            o.y = w4.y - s[b] * a4.y;
            o.z = w4.z - s[b] * a4.z;
            o.w = w4.w - s[b] * a4.w;
            __stcs((float4*)(dst + (size_t)b * D1 * DKK), o);
        }
    } else {
        int idx = bx - 4096;
        int h   = idx >> 2;
        int off = (idx & 3) * 1024;
        float s[B];
#pragma unroll
        for (int b = 0; b < B; b++) s[b] = LRC * g_dHt[h * B + b];
        float4 w4 = __ldg((const float4*)(W1 + (size_t)h * D1 + off + col));
        float* dst = out_w1 + (size_t)h * D1 + off + col;
#pragma unroll 4
        for (int b = 0; b < B; b++) {
            float4 a4 = *(const float4*)(g_G + b * D1 + off + col);
            float4 o;
            o.x = w4.x - s[b] * a4.x;
            o.y = w4.y - s[b] * a4.y;
            o.z = w4.z - s[b] * a4.z;
            o.w = w4.w - s[b] * a4.w;
            __stcs((float4*)(dst + (size_t)b * HH * D1), o);
        }
    }
}

extern "C" void kernel_launch(void* const* d_in, const int* in_sizes, int n_in,
                              void* d_out, int out_size) {
    const float* x  = (const float*)d_in[0];
    const float* Wk = (const float*)d_in[1];
    const float* Wv = (const float*)d_in[2];
    const float* Wo = (const float*)d_in[3];
    const float* W0 = (const float*)d_in[4];
    const float* W1 = (const float*)d_in[5];

    float* out    = (float*)d_out;
    float* out_w0 = out + (size_t)B * IN;
    float* out_w1 = out_w0 + (size_t)B * D1 * DKK;

    proj_kernel  <<<256, 256>>>(x, Wk, Wv);             // 2048 warps
    zgelu_kernel <<<512, 256>>>(W0);                    // 4096 warps
    hdh_kernel   <<<512, 256>>>(W1);                    // 1024 rows, split-4
    dgpart_kernel<<<dim3(D1 / 256, NCH, 1), 256>>>(W1); // 512 blocks
    dz_kernel    <<<(B * D1) / 256, 256>>>();
    out_kernel   <<<256, 256>>>(Wo, out);               // 1024 rows, split-2
    update_kernel<<<8192, 256>>>(W0, W1, out_w0, out_w1);
}

// round 3
// speedup vs baseline: 2.5059x; 1.0008x over previous
#include <cuda_runtime.h>
#include <math.h>

#define B    16
#define IN   1024
#define HH   1024
#define DKK  1024
#define D1   4096
#define LRC  0.01f
#define NCH  32
#define CI   32              // rows of W1 per dG chunk

// ---------------- scratch (allocation-free) ----------------
__device__ __align__(16) float g_K  [B * DKK];        // b-major
__device__ __align__(16) float g_V  [B * HH];         // b-major
__device__ __align__(16) float g_G  [B * D1];         // b-major
__device__ __align__(16) float g_Gp [B * D1];         // b-major
__device__ __align__(16) float g_Hd [B * HH];         // b-major
__device__ __align__(16) float g_dHt[HH * B];         // i-major
__device__ __align__(16) float g_part[NCH * B * D1];  // 8 MB partials

__device__ __forceinline__ float warp_sum(float v) {
    v += __shfl_xor_sync(0xffffffffu, v, 16);
    v += __shfl_xor_sync(0xffffffffu, v, 8);
    v += __shfl_xor_sync(0xffffffffu, v, 4);
    v += __shfl_xor_sync(0xffffffffu, v, 2);
    v += __shfl_xor_sync(0xffffffffu, v, 1);
    return v;
}
__device__ __forceinline__ float dot4(float4 a, float4 b) {
    return a.x * b.x + a.y * b.y + a.z * b.z + a.w * b.w;
}

// ---------------- K = X @ Wk^T, V = X @ Wv^T (warp per (m,j)) ----------------
__global__ void proj_kernel(const float* __restrict__ X,
                            const float* __restrict__ Wk,
                            const float* __restrict__ Wv) {
    int gw   = (blockIdx.x * blockDim.x + threadIdx.x) >> 5;
    int lane = threadIdx.x & 31;
    int m = gw >> 10;
    int j = gw & 1023;
    const float* wrow = (m ? Wv : Wk) + (size_t)j * IN;

    float acc[B];
#pragma unroll
    for (int b = 0; b < B; b++) acc[b] = 0.f;

#pragma unroll 2
    for (int it = 0; it < 8; it++) {
        int i0 = it * 128 + lane * 4;
        float4 w4 = __ldg((const float4*)(wrow + i0));
#pragma unroll
        for (int b = 0; b < B; b++) {
            float4 x4 = __ldg((const float4*)(X + b * IN + i0));
            acc[b] += dot4(w4, x4);
        }
    }
#pragma unroll
    for (int b = 0; b < B; b++) acc[b] = warp_sum(acc[b]);
    if (lane == 0) {
        float* out = m ? g_V : g_K;
#pragma unroll
        for (int b = 0; b < B; b++) out[b * 1024 + j] = acc[b];
    }
}

// ---------------- Z = K @ W0^T ; G = gelu(Z), Gp = gelu'(Z) (warp per 2 rows) ----------------
__global__ void zgelu_kernel(const float* __restrict__ W0) {
    int gw   = (blockIdx.x * blockDim.x + threadIdx.x) >> 5;  // 0..2047
    int lane = threadIdx.x & 31;
    int j0 = gw * 2;
    const float* wrow0 = W0 + (size_t)j0 * DKK;
    const float* wrow1 = wrow0 + DKK;

    float acc0[B], acc1[B];
#pragma unroll
    for (int b = 0; b < B; b++) { acc0[b] = 0.f; acc1[b] = 0.f; }

#pragma unroll 2
    for (int it = 0; it < 8; it++) {
        int i0 = it * 128 + lane * 4;
        float4 wa = __ldg((const float4*)(wrow0 + i0));
        float4 wb = __ldg((const float4*)(wrow1 + i0));
#pragma unroll
        for (int b = 0; b < B; b++) {
            float4 k4 = *(const float4*)(g_K + b * DKK + i0);
            acc0[b] += dot4(wa, k4);
            acc1[b] += dot4(wb, k4);
        }
    }
#pragma unroll
    for (int b = 0; b < B; b++) { acc0[b] = warp_sum(acc0[b]); acc1[b] = warp_sum(acc1[b]); }
    if (lane == 0) {
#pragma unroll
        for (int b = 0; b < B; b++) {
#pragma unroll
            for (int r = 0; r < 2; r++) {
                float z  = r ? acc1[b] : acc0[b];
                float c  = 0.5f * (1.f + erff(z * 0.70710678118654752f));
                float g  = z * c;
                float gp = c + z * 0.39894228040143268f * expf(-0.5f * z * z);
                g_G [b * D1 + j0 + r] = g;
                g_Gp[b * D1 + j0 + r] = gp;
            }
        }
    }
}

// ---------------- Hd = G @ W1^T ; dH = (Hd - V)/H (split-4, 2 rows/block) ----------------
__global__ void hdh_kernel(const float* __restrict__ W1) {
    __shared__ float sm[2][4][B];
    int w    = threadIdx.x >> 5;
    int lane = threadIdx.x & 31;
    int r = w >> 2;
    int s = w & 3;
    int i = blockIdx.x * 2 + r;
    const float* wrow = W1 + (size_t)i * D1 + s * 1024;

    float acc[B];
#pragma unroll
    for (int b = 0; b < B; b++) acc[b] = 0.f;

#pragma unroll 2
    for (int it = 0; it < 8; it++) {
        int j0 = it * 128 + lane * 4;
        float4 w4 = __ldg((const float4*)(wrow + j0));
#pragma unroll
        for (int b = 0; b < B; b++) {
            float4 g4 = *(const float4*)(g_G + b * D1 + s * 1024 + j0);
            acc[b] += dot4(w4, g4);
        }
    }
#pragma unroll
    for (int b = 0; b < B; b++) acc[b] = warp_sum(acc[b]);
    if (lane == 0) {
#pragma unroll
        for (int b = 0; b < B; b++) sm[r][s][b] = acc[b];
    }
    __syncthreads();
    if (threadIdx.x < 32) {
        int rr = threadIdx.x >> 4;
        int b  = threadIdx.x & 15;
        int ii = blockIdx.x * 2 + rr;
        float h = sm[rr][0][b] + sm[rr][1][b] + sm[rr][2][b] + sm[rr][3][b];
        g_Hd [b * HH + ii] = h;
        g_dHt[ii * B + b]  = (h - g_V[b * HH + ii]) * (1.0f / (float)HH);
    }
}

// ---------------- output = Hd @ Wo^T (split-2, 4 rows/block) ----------------
__global__ void out_kernel(const float* __restrict__ Wo, float* __restrict__ out) {
    __shared__ float sm[4][2][B];
    int w    = threadIdx.x >> 5;
    int lane = threadIdx.x & 31;
    int r = w >> 1;
    int s = w & 1;
    int n = blockIdx.x * 4 + r;
    const float* wrow = Wo + (size_t)n * HH + s * 512;

    float acc[B];
#pragma unroll
    for (int b = 0; b < B; b++) acc[b] = 0.f;

#pragma unroll 2
    for (int it = 0; it < 4; it++) {
        int h0 = it * 128 + lane * 4;
        float4 w4 = __ldg((const float4*)(wrow + h0));
#pragma unroll
        for (int b = 0; b < B; b++) {
            float4 h4 = *(const float4*)(g_Hd + b * HH + s * 512 + h0);
            acc[b] += dot4(w4, h4);
        }
    }
#pragma unroll
    for (int b = 0; b < B; b++) acc[b] = warp_sum(acc[b]);
    if (lane == 0) {
#pragma unroll
        for (int b = 0; b < B; b++) sm[r][s][b] = acc[b];
    }
    __syncthreads();
    if (threadIdx.x < 64) {
        int rr = threadIdx.x >> 4;
        int b  = threadIdx.x & 15;
        int nn = blockIdx.x * 4 + rr;
        out[b * IN + nn] = sm[rr][0][b] + sm[rr][1][b];
    }
}

// ---------------- FUSED: dG partials + W1 update ----------------
// block = (chunk c of 32 i-rows) x (512-wide j tile); thread owns 2 j's.
// Each W1 element loaded once; feeds acc partials AND 16 streaming stores.
__global__ void fused_w1_kernel(const float* __restrict__ W1,
                                float* __restrict__ out_w1) {
    __shared__ float sdh[CI * B];   // dH for this chunk, [i][b]
    int tid = threadIdx.x;
    int c   = blockIdx.y;
    int i0  = c * CI;
    int j   = blockIdx.x * 512 + tid * 2;

    sdh[tid]       = g_dHt[i0 * B + tid];
    sdh[tid + 256] = g_dHt[i0 * B + tid + 256];
    __syncthreads();

    float2 gg[B];
#pragma unroll
    for (int b = 0; b < B; b++) gg[b] = *(const float2*)(g_G + b * D1 + j);

    float2 acc[B];
#pragma unroll
    for (int b = 0; b < B; b++) { acc[b].x = 0.f; acc[b].y = 0.f; }

#pragma unroll 4
    for (int r = 0; r < CI; r++) {
        int i = i0 + r;
        float2 w2 = __ldg((const float2*)(W1 + (size_t)i * D1 + j));
        float* dst = out_w1 + (size_t)i * D1 + j;
#pragma unroll
        for (int b = 0; b < B; b++) {
            float dh = sdh[r * B + b];
            acc[b].x += dh * w2.x;
            acc[b].y += dh * w2.y;
            float t = LRC * dh;
            float2 o;
            o.x = w2.x - t * gg[b].x;
            o.y = w2.y - t * gg[b].y;
            __stcs((float2*)(dst + (size_t)b * HH * D1), o);
        }
    }
#pragma unroll
    for (int b = 0; b < B; b++)
        *(float2*)(g_part + ((size_t)c * B + b) * D1 + j) = acc[b];
}

// ---------------- FUSED: dZ reduction + W0 update ----------------
// block = one d1 row; reduce partials -> dZ[b] in smem, then stream 16 rows.
__global__ void fused_w0_kernel(const float* __restrict__ W0,
                                float* __restrict__ out_w0) {
    __shared__ float s_red[B][17];
    __shared__ float s_dz[B];
    int tid = threadIdx.x;
    int d1  = blockIdx.x;

    {
        int b = tid >> 4;
        int l = tid & 15;
        float p = g_part[((size_t)l        * B + b) * D1 + d1]
                + g_part[((size_t)(l + 16) * B + b) * D1 + d1];
        s_red[b][l] = p;
    }
    __syncthreads();
    if (tid < B) {
        float s = 0.f;
#pragma unroll
        for (int l = 0; l < 16; l++) s += s_red[tid][l];
        s_dz[tid] = LRC * s * g_Gp[tid * D1 + d1];
    }
    __syncthreads();

    int col = tid * 4;
    float4 w4 = __ldg((const float4*)(W0 + (size_t)d1 * DKK + col));
    float* dst = out_w0 + (size_t)d1 * DKK + col;
#pragma unroll 4
    for (int b = 0; b < B; b++) {
        float s = s_dz[b];
        float4 a4 = *(const float4*)(g_K + b * DKK + col);
        float4 o;
        o.x = w4.x - s * a4.x;
        o.y = w4.y - s * a4.y;
        o.z = w4.z - s * a4.z;
        o.w = w4.w - s * a4.w;
        __stcs((float4*)(dst + (size_t)b * D1 * DKK), o);
    }
}

extern "C" void kernel_launch(void* const* d_in, const int* in_sizes, int n_in,
                              void* d_out, int out_size) {
    const float* x  = (const float*)d_in[0];
    const float* Wk = (const float*)d_in[1];
    const float* Wv = (const float*)d_in[2];
    const float* Wo = (const float*)d_in[3];
    const float* W0 = (const float*)d_in[4];
    const float* W1 = (const float*)d_in[5];

    float* out    = (float*)d_out;
    float* out_w0 = out + (size_t)B * IN;
    float* out_w1 = out_w0 + (size_t)B * D1 * DKK;

    proj_kernel    <<<256, 256>>>(x, Wk, Wv);
    zgelu_kernel   <<<256, 256>>>(W0);                 // 2048 warps, 2 rows each
    hdh_kernel     <<<512, 256>>>(W1);
    out_kernel     <<<256, 256>>>(Wo, out);
    fused_w1_kernel<<<dim3(D1 / 512, NCH), 256>>>(W1, out_w1);
    fused_w0_kernel<<<D1, 256>>>(W0, out_w0);
}

// round 4
// speedup vs baseline: 2.5069x; 1.0004x over previous
#include <cuda_runtime.h>
#include <math.h>

#define B    16
#define IN   1024
#define HH   1024
#define DKK  1024
#define D1   4096
#define LRC  0.01f
#define NCH  64
#define CI   16              // rows of W1 per dG chunk

// ---------------- scratch (allocation-free) ----------------
__device__ __align__(16) float g_K  [B * DKK];        // b-major
__device__ __align__(16) float g_V  [B * HH];         // b-major
__device__ __align__(16) float g_G  [B * D1];         // b-major
__device__ __align__(16) float g_Gp [B * D1];         // b-major
__device__ __align__(16) float g_Hd [B * HH];         // b-major
__device__ __align__(16) float g_dHt[HH * B];         // i-major
__device__ __align__(16) float g_part[NCH * B * D1];  // 16 MB partials

__device__ __forceinline__ float warp_sum(float v) {
    v += __shfl_xor_sync(0xffffffffu, v, 16);
    v += __shfl_xor_sync(0xffffffffu, v, 8);
    v += __shfl_xor_sync(0xffffffffu, v, 4);
    v += __shfl_xor_sync(0xffffffffu, v, 2);
    v += __shfl_xor_sync(0xffffffffu, v, 1);
    return v;
}
__device__ __forceinline__ float dot4(float4 a, float4 b) {
    return a.x * b.x + a.y * b.y + a.z * b.z + a.w * b.w;
}

// ---------------- K = X @ Wk^T, V = X @ Wv^T (split-K2, warp per half-row) ----------------
__global__ void proj_kernel(const float* __restrict__ X,
                            const float* __restrict__ Wk,
                            const float* __restrict__ Wv) {
    __shared__ float sm[8][B];
    int w    = threadIdx.x >> 5;
    int lane = threadIdx.x & 31;
    int task = blockIdx.x * 8 + w;          // 0..4095
    int half = task & 1;
    int rowg = task >> 1;                   // 0..2047
    int m = rowg >> 10;
    int j = rowg & 1023;
    const float* wrow = (m ? Wv : Wk) + (size_t)j * IN + half * 512;
    const float* xs   = X + half * 512;

    float acc[B];
#pragma unroll
    for (int b = 0; b < B; b++) acc[b] = 0.f;

#pragma unroll 4
    for (int it = 0; it < 4; it++) {
        int i0 = it * 128 + lane * 4;
        float4 w4 = __ldg((const float4*)(wrow + i0));
#pragma unroll
        for (int b = 0; b < B; b++) {
            float4 x4 = __ldg((const float4*)(xs + b * IN + i0));
            acc[b] += dot4(w4, x4);
        }
    }
#pragma unroll
    for (int b = 0; b < B; b++) acc[b] = warp_sum(acc[b]);
    if (lane == 0) {
#pragma unroll
        for (int b = 0; b < B; b++) sm[w][b] = acc[b];
    }
    __syncthreads();
    if (threadIdx.x < 64) {
        int p = threadIdx.x >> 4;          // pair 0..3
        int b = threadIdx.x & 15;
        int rg = blockIdx.x * 4 + p;       // global row 0..2047
        float v = sm[2 * p][b] + sm[2 * p + 1][b];
        float* out = (rg >> 10) ? g_V : g_K;
        out[b * 1024 + (rg & 1023)] = v;
    }
}

// ---------------- Z = K @ W0^T ; G = gelu(Z), Gp = gelu'(Z) (warp per row) ----------------
__global__ void zgelu_kernel(const float* __restrict__ W0) {
    int j    = (blockIdx.x * blockDim.x + threadIdx.x) >> 5;   // 0..4095
    int lane = threadIdx.x & 31;
    const float* wrow = W0 + (size_t)j * DKK;

    float acc[B];
#pragma unroll
    for (int b = 0; b < B; b++) acc[b] = 0.f;

#pragma unroll 4
    for (int it = 0; it < 8; it++) {
        int i0 = it * 128 + lane * 4;
        float4 w4 = __ldg((const float4*)(wrow + i0));
#pragma unroll
        for (int b = 0; b < B; b++) {
            float4 k4 = *(const float4*)(g_K + b * DKK + i0);
            acc[b] += dot4(w4, k4);
        }
    }
#pragma unroll
    for (int b = 0; b < B; b++) acc[b] = warp_sum(acc[b]);
    if (lane == 0) {
#pragma unroll
        for (int b = 0; b < B; b++) {
            float z  = acc[b];
            float c  = 0.5f * (1.f + erff(z * 0.70710678118654752f));
            float g  = z * c;
            float gp = c + z * 0.39894228040143268f * expf(-0.5f * z * z);
            g_G [b * D1 + j] = g;
            g_Gp[b * D1 + j] = gp;
        }
    }
}

// ---------------- Hd = G @ W1^T ; dH = (Hd - V)/H (split-4, 2 rows/block) ----------------
__global__ void hdh_kernel(const float* __restrict__ W1) {
    __shared__ float sm[2][4][B];
    int w    = threadIdx.x >> 5;
    int lane = threadIdx.x & 31;
    int r = w >> 2;
    int s = w & 3;
    int i = blockIdx.x * 2 + r;
    const float* wrow = W1 + (size_t)i * D1 + s * 1024;

    float acc[B];
#pragma unroll
    for (int b = 0; b < B; b++) acc[b] = 0.f;

#pragma unroll 4
    for (int it = 0; it < 8; it++) {
        int j0 = it * 128 + lane * 4;
        float4 w4 = __ldg((const float4*)(wrow + j0));
#pragma unroll
        for (int b = 0; b < B; b++) {
            float4 g4 = *(const float4*)(g_G + b * D1 + s * 1024 + j0);
            acc[b] += dot4(w4, g4);
        }
    }
#pragma unroll
    for (int b = 0; b < B; b++) acc[b] = warp_sum(acc[b]);
    if (lane == 0) {
#pragma unroll
        for (int b = 0; b < B; b++) sm[r][s][b] = acc[b];
    }
    __syncthreads();
    if (threadIdx.x < 32) {
        int rr = threadIdx.x >> 4;
        int b  = threadIdx.x & 15;
        int ii = blockIdx.x * 2 + rr;
        float h = sm[rr][0][b] + sm[rr][1][b] + sm[rr][2][b] + sm[rr][3][b];
        g_Hd [b * HH + ii] = h;
        g_dHt[ii * B + b]  = (h - g_V[b * HH + ii]) * (1.0f / (float)HH);
    }
}

// ---------------- MEGA: W1 update + dG partials (blocks 0..255)  |  output GEMV (blocks 256..511) ----------------
__global__ void fused_w1_out_kernel(const float* __restrict__ W1,
                                    const float* __restrict__ Wo,
                                    float* __restrict__ out_w1,
                                    float* __restrict__ out) {
    int tid = threadIdx.x;
    if (blockIdx.x < 256) {
        // ---- W1 update + partials: chunk c (16 i-rows) x 1024-j tile ----
        __shared__ float sdh[CI * B];
        int c  = blockIdx.x >> 2;           // 0..63
        int jt = blockIdx.x & 3;
        int i0 = c * CI;
        int j  = jt * 1024 + tid * 4;

        sdh[tid] = g_dHt[i0 * B + tid];     // 16 rows x 16 b
        __syncthreads();

#pragma unroll
        for (int half = 0; half < 2; half++) {
            float4 gg[8], acc[8];
#pragma unroll
            for (int bb = 0; bb < 8; bb++) {
                gg[bb] = *(const float4*)(g_G + (half * 8 + bb) * D1 + j);
                acc[bb] = make_float4(0.f, 0.f, 0.f, 0.f);
            }
#pragma unroll 4
            for (int r = 0; r < CI; r++) {
                int i = i0 + r;
                float4 w4 = __ldg((const float4*)(W1 + (size_t)i * D1 + j));
                float* dst = out_w1 + (size_t)i * D1 + j;
#pragma unroll
                for (int bb = 0; bb < 8; bb++) {
                    int b = half * 8 + bb;
                    float dh = sdh[r * B + b];
                    acc[bb].x += dh * w4.x;
                    acc[bb].y += dh * w4.y;
                    acc[bb].z += dh * w4.z;
                    acc[bb].w += dh * w4.w;
                    float t = LRC * dh;
                    float4 o;
                    o.x = w4.x - t * gg[bb].x;
                    o.y = w4.y - t * gg[bb].y;
                    o.z = w4.z - t * gg[bb].z;
                    o.w = w4.w - t * gg[bb].w;
                    __stcs((float4*)(dst + (size_t)b * HH * D1), o);
                }
            }
#pragma unroll
            for (int bb = 0; bb < 8; bb++)
                *(float4*)(g_part + ((size_t)c * B + half * 8 + bb) * D1 + j) = acc[bb];
        }
    } else {
        // ---- output = Hd @ Wo^T (split-2, 4 rows/block) ----
        __shared__ float sm[4][2][B];
        int bx2  = blockIdx.x - 256;
        int w    = tid >> 5;
        int lane = tid & 31;
        int r = w >> 1;
        int s = w & 1;
        int n = bx2 * 4 + r;
        const float* wrow = Wo + (size_t)n * HH + s * 512;

        float acc[B];
#pragma unroll
        for (int b = 0; b < B; b++) acc[b] = 0.f;

#pragma unroll 4
        for (int it = 0; it < 4; it++) {
            int h0 = it * 128 + lane * 4;
            float4 w4 = __ldg((const float4*)(wrow + h0));
#pragma unroll
            for (int b = 0; b < B; b++) {
                float4 h4 = *(const float4*)(g_Hd + b * HH + s * 512 + h0);
                acc[b] += dot4(w4, h4);
            }
        }
#pragma unroll
        for (int b = 0; b < B; b++) acc[b] = warp_sum(acc[b]);
        if (lane == 0) {
#pragma unroll
            for (int b = 0; b < B; b++) sm[r][s][b] = acc[b];
        }
        __syncthreads();
        if (tid < 64) {
            int rr = tid >> 4;
            int b  = tid & 15;
            int nn = bx2 * 4 + rr;
            out[b * IN + nn] = sm[rr][0][b] + sm[rr][1][b];
        }
    }
}

// ---------------- FUSED: dZ reduction + W0 update (block per d1 row) ----------------
__global__ void fused_w0_kernel(const float* __restrict__ W0,
                                float* __restrict__ out_w0) {
    __shared__ float s_red[B][17];
    __shared__ float s_dz[B];
    int tid = threadIdx.x;
    int d1  = blockIdx.x;

    {
        int b = tid >> 4;
        int l = tid & 15;
        float p = 0.f;
#pragma unroll
        for (int q = 0; q < 4; q++)
            p += g_part[((size_t)(l + 16 * q) * B + b) * D1 + d1];
        s_red[b][l] = p;
    }
    __syncthreads();
    if (tid < B) {
        float s = 0.f;
#pragma unroll
        for (int l = 0; l < 16; l++) s += s_red[tid][l];
        s_dz[tid] = LRC * s * g_Gp[tid * D1 + d1];
    }
    __syncthreads();

    int col = tid * 4;
    float4 w4 = __ldg((const float4*)(W0 + (size_t)d1 * DKK + col));
    float* dst = out_w0 + (size_t)d1 * DKK + col;
#pragma unroll 4
    for (int b = 0; b < B; b++) {
        float s = s_dz[b];
        float4 a4 = *(const float4*)(g_K + b * DKK + col);
        float4 o;
        o.x = w4.x - s * a4.x;
        o.y = w4.y - s * a4.y;
        o.z = w4.z - s * a4.z;
        o.w = w4.w - s * a4.w;
        __stcs((float4*)(dst + (size_t)b * D1 * DKK), o);
    }
}

extern "C" void kernel_launch(void* const* d_in, const int* in_sizes, int n_in,
                              void* d_out, int out_size) {
    const float* x  = (const float*)d_in[0];
    const float* Wk = (const float*)d_in[1];
    const float* Wv = (const float*)d_in[2];
    const float* Wo = (const float*)d_in[3];
    const float* W0 = (const float*)d_in[4];
    const float* W1 = (const float*)d_in[5];

    float* out    = (float*)d_out;
    float* out_w0 = out + (size_t)B * IN;
    float* out_w1 = out_w0 + (size_t)B * D1 * DKK;

    proj_kernel       <<<512, 256>>>(x, Wk, Wv);     // split-K2, 4096 warps
    zgelu_kernel      <<<512, 256>>>(W0);            // 4096 warps
    hdh_kernel        <<<512, 256>>>(W1);            // split-4
    fused_w1_out_kernel<<<512, 256>>>(W1, Wo, out_w1, out);
    fused_w0_kernel   <<<D1, 256>>>(W0, out_w0);
}

// round 5
// speedup vs baseline: 2.7950x; 1.1149x over previous
#include <cuda_runtime.h>
#include <math.h>

#define B    16
#define IN   1024
#define HH   1024
#define DKK  1024
#define D1   4096
#define LRC  0.01f
#define NCH  32
#define CI   32

// ---------------- scratch (allocation-free) ----------------
__device__ __align__(16) float g_K  [B * DKK];          // b-major
__device__ __align__(16) float g_V  [B * HH];           // b-major
__device__ __align__(16) float g_G  [B * D1];           // b-major
__device__ __align__(16) float g_Gp [B * D1];           // b-major
__device__ __align__(16) float g_Hd [B * HH];           // b-major
__device__ __align__(16) float g_dHt[HH * B];           // i-major
__device__ __align__(16) float g_part[NCH * B * D1];    // [c][b][j], 8 MB

__device__ __forceinline__ float warp_sum(float v) {
    v += __shfl_xor_sync(0xffffffffu, v, 16);
    v += __shfl_xor_sync(0xffffffffu, v, 8);
    v += __shfl_xor_sync(0xffffffffu, v, 4);
    v += __shfl_xor_sync(0xffffffffu, v, 2);
    v += __shfl_xor_sync(0xffffffffu, v, 1);
    return v;
}
__device__ __forceinline__ float dot4(float4 a, float4 b) {
    return a.x * b.x + a.y * b.y + a.z * b.z + a.w * b.w;
}

// ---------------- proj: rows 0..1023 -> K, 1024..2047 -> V ----------------
// warp owns 4 rows x 16 b x half of I; 128 blocks x 256 thr
__global__ void proj_kernel(const float* __restrict__ X,
                            const float* __restrict__ Wk,
                            const float* __restrict__ Wv) {
    __shared__ float sm[4][2][64];
    int w = threadIdx.x >> 5, lane = threadIdx.x & 31;
    int rgl = w >> 1, half = w & 1;
    int rg = blockIdx.x * 4 + rgl;            // 0..511
    const float* Wb = (rg >> 8) ? Wv : Wk;
    int row0 = (rg * 4) & 1023;
    int ibase = half * 512;
    const float* wp = Wb + (size_t)row0 * IN + ibase;
    const float* xp = X + ibase;

    float acc[4][16];
#pragma unroll
    for (int r = 0; r < 4; r++)
#pragma unroll
        for (int b = 0; b < 16; b++) acc[r][b] = 0.f;

#pragma unroll
    for (int it = 0; it < 4; it++) {
        int i = it * 128 + lane * 4;
        float4 wv[4];
#pragma unroll
        for (int r = 0; r < 4; r++) wv[r] = __ldg((const float4*)(wp + r * IN + i));
#pragma unroll
        for (int b = 0; b < 16; b++) {
            float4 x4 = __ldg((const float4*)(xp + b * IN + i));
#pragma unroll
            for (int r = 0; r < 4; r++) acc[r][b] += dot4(wv[r], x4);
        }
    }
#pragma unroll
    for (int r = 0; r < 4; r++)
#pragma unroll
        for (int b = 0; b < 16; b++) acc[r][b] = warp_sum(acc[r][b]);
    if (lane == 0) {
#pragma unroll
        for (int r = 0; r < 4; r++)
#pragma unroll
            for (int b = 0; b < 16; b++) sm[rgl][half][r * 16 + b] = acc[r][b];
    }
    __syncthreads();
    {
        int t = threadIdx.x;
        int rg2 = t >> 6, r = (t >> 4) & 3, b = t & 15;
        float v = sm[rg2][0][r * 16 + b] + sm[rg2][1][r * 16 + b];
        int row = (blockIdx.x * 4 + rg2) * 4 + r;
        float* o = (row >> 10) ? g_V : g_K;
        o[b * 1024 + (row & 1023)] = v;
    }
}

// ---------------- zgelu: Z = K @ W0^T ; G, Gp. 256 blocks x 256 thr ----------------
__global__ void zgelu_kernel(const float* __restrict__ W0) {
    __shared__ float sm[4][2][64];
    int w = threadIdx.x >> 5, lane = threadIdx.x & 31;
    int rgl = w >> 1, half = w & 1;
    int rg = blockIdx.x * 4 + rgl;            // 0..1023
    int j0 = rg * 4;
    int ibase = half * 512;
    const float* wp = W0 + (size_t)j0 * DKK + ibase;

    float acc[4][16];
#pragma unroll
    for (int r = 0; r < 4; r++)
#pragma unroll
        for (int b = 0; b < 16; b++) acc[r][b] = 0.f;

#pragma unroll
    for (int it = 0; it < 4; it++) {
        int i = it * 128 + lane * 4;
        float4 wv[4];
#pragma unroll
        for (int r = 0; r < 4; r++) wv[r] = __ldg((const float4*)(wp + r * DKK + i));
#pragma unroll
        for (int b = 0; b < 16; b++) {
            float4 k4 = *(const float4*)(g_K + b * DKK + ibase + i);
#pragma unroll
            for (int r = 0; r < 4; r++) acc[r][b] += dot4(wv[r], k4);
        }
    }
#pragma unroll
    for (int r = 0; r < 4; r++)
#pragma unroll
        for (int b = 0; b < 16; b++) acc[r][b] = warp_sum(acc[r][b]);
    if (lane == 0) {
#pragma unroll
        for (int r = 0; r < 4; r++)
#pragma unroll
            for (int b = 0; b < 16; b++) sm[rgl][half][r * 16 + b] = acc[r][b];
    }
    __syncthreads();
    {
        int t = threadIdx.x;
        int rg2 = t >> 6, r = (t >> 4) & 3, b = t & 15;
        float z = sm[rg2][0][r * 16 + b] + sm[rg2][1][r * 16 + b];
        int j = (blockIdx.x * 4 + rg2) * 4 + r;
        float c  = 0.5f * (1.f + erff(z * 0.70710678118654752f));
        float g  = z * c;
        float gp = c + z * 0.39894228040143268f * expf(-0.5f * z * z);
        g_G [b * D1 + j] = g;
        g_Gp[b * D1 + j] = gp;
    }
}

// ---------------- hdh: Hd = G @ W1^T ; dH. 128 blocks x 256 thr ----------------
__global__ void hdh_kernel(const float* __restrict__ W1) {
    __shared__ float sm[2][4][64];
    int w = threadIdx.x >> 5, lane = threadIdx.x & 31;
    int rgl = w >> 2, s = w & 3;
    int rg = blockIdx.x * 2 + rgl;            // 0..255
    int i0 = rg * 4;
    int jbase = s * 1024;
    const float* wp = W1 + (size_t)i0 * D1 + jbase;

    float acc[4][16];
#pragma unroll
    for (int r = 0; r < 4; r++)
#pragma unroll
        for (int b = 0; b < 16; b++) acc[r][b] = 0.f;

#pragma unroll
    for (int it = 0; it < 8; it++) {
        int j = it * 128 + lane * 4;
        float4 wv[4];
#pragma unroll
        for (int r = 0; r < 4; r++) wv[r] = __ldg((const float4*)(wp + r * D1 + j));
#pragma unroll
        for (int b = 0; b < 16; b++) {
            float4 g4 = *(const float4*)(g_G + b * D1 + jbase + j);
#pragma unroll
            for (int r = 0; r < 4; r++) acc[r][b] += dot4(wv[r], g4);
        }
    }
#pragma unroll
    for (int r = 0; r < 4; r++)
#pragma unroll
        for (int b = 0; b < 16; b++) acc[r][b] = warp_sum(acc[r][b]);
    if (lane == 0) {
#pragma unroll
        for (int r = 0; r < 4; r++)
#pragma unroll
            for (int b = 0; b < 16; b++) sm[rgl][s][r * 16 + b] = acc[r][b];
    }
    __syncthreads();
    if (threadIdx.x < 128) {
        int t = threadIdx.x;
        int rg2 = t >> 6, r = (t >> 4) & 3, b = t & 15;
        float h = sm[rg2][0][r * 16 + b] + sm[rg2][1][r * 16 + b]
                + sm[rg2][2][r * 16 + b] + sm[rg2][3][r * 16 + b];
        int i = (blockIdx.x * 2 + rg2) * 4 + r;
        g_Hd [b * HH + i] = h;
        g_dHt[i * B + b]  = (h - g_V[b * HH + i]) * (1.0f / (float)HH);
    }
}

// ---------------- fused: W1 update + dG partials (blocks 0..255) | output GEMV (256..319) ----------------
// 128 threads per block.
__global__ void fused_w1_out_kernel(const float* __restrict__ W1,
                                    const float* __restrict__ Wo,
                                    float* __restrict__ out_w1,
                                    float* __restrict__ out) {
    __shared__ float sdh[CI * B];
    int tid = threadIdx.x;
    if (blockIdx.x < 256) {
        int c  = blockIdx.x >> 3;             // 0..31
        int jt = blockIdx.x & 7;              // 0..7
        int i0 = c * CI;
        int j  = jt * 512 + tid * 4;

        sdh[tid]       = g_dHt[i0 * B + tid];
        sdh[tid + 128] = g_dHt[i0 * B + tid + 128];
        sdh[tid + 256] = g_dHt[i0 * B + tid + 256];
        sdh[tid + 384] = g_dHt[i0 * B + tid + 384];
        __syncthreads();

#pragma unroll
        for (int half = 0; half < 2; half++) {
            float4 gg[8], acc[8];
#pragma unroll
            for (int bb = 0; bb < 8; bb++) {
                gg[bb]  = *(const float4*)(g_G + (half * 8 + bb) * D1 + j);
                acc[bb] = make_float4(0.f, 0.f, 0.f, 0.f);
            }
#pragma unroll 4
            for (int r = 0; r < CI; r++) {
                int i = i0 + r;
                float4 w4 = __ldg((const float4*)(W1 + (size_t)i * D1 + j));
                float* dst = out_w1 + (size_t)i * D1 + j;
#pragma unroll
                for (int bb = 0; bb < 8; bb++) {
                    int b = half * 8 + bb;
                    float dh = sdh[r * B + b];
                    acc[bb].x += dh * w4.x;
                    acc[bb].y += dh * w4.y;
                    acc[bb].z += dh * w4.z;
                    acc[bb].w += dh * w4.w;
                    float t = LRC * dh;
                    float4 o;
                    o.x = w4.x - t * gg[bb].x;
                    o.y = w4.y - t * gg[bb].y;
                    o.z = w4.z - t * gg[bb].z;
                    o.w = w4.w - t * gg[bb].w;
                    __stcs((float4*)(dst + (size_t)b * HH * D1), o);
                }
            }
#pragma unroll
            for (int bb = 0; bb < 8; bb++)
                *(float4*)(g_part + ((size_t)c * B + half * 8 + bb) * D1 + j) = acc[bb];
        }
    } else {
        // output = Hd @ Wo^T : 64 blocks x 4 warps, warp owns 4 rows, full I
        int w = tid >> 5, lane = tid & 31;
        int n0 = ((blockIdx.x - 256) * 4 + w) * 4;    // 0..1020
        const float* wp = Wo + (size_t)n0 * HH;

        float acc[4][16];
#pragma unroll
        for (int r = 0; r < 4; r++)
#pragma unroll
            for (int b = 0; b < 16; b++) acc[r][b] = 0.f;

#pragma unroll
        for (int it = 0; it < 8; it++) {
            int i = it * 128 + lane * 4;
            float4 wv[4];
#pragma unroll
            for (int r = 0; r < 4; r++) wv[r] = __ldg((const float4*)(wp + r * HH + i));
#pragma unroll
            for (int b = 0; b < 16; b++) {
                float4 h4 = *(const float4*)(g_Hd + b * HH + i);
#pragma unroll
                for (int r = 0; r < 4; r++) acc[r][b] += dot4(wv[r], h4);
            }
        }
#pragma unroll
        for (int r = 0; r < 4; r++)
#pragma unroll
            for (int b = 0; b < 16; b++) acc[r][b] = warp_sum(acc[r][b]);
        if (lane == 0) {
#pragma unroll
            for (int r = 0; r < 4; r++)
#pragma unroll
                for (int b = 0; b < 16; b++) out[b * IN + n0 + r] = acc[r][b];
        }
    }
}

// ---------------- fused: dZ reduce + W0 update. 256 blocks x 256 thr, 16 d1-rows each ----------------
__global__ void fused_w0_kernel(const float* __restrict__ W0,
                                float* __restrict__ out_w0) {
    __shared__ float sp[NCH * 257];
    __shared__ float sdz[256];                 // [b][r]
    int tid  = threadIdx.x;
    int d1_0 = blockIdx.x * 16;

#pragma unroll 4
    for (int c = 0; c < NCH; c++)
        sp[c * 257 + tid] = g_part[((size_t)c * B + (tid >> 4)) * D1 + d1_0 + (tid & 15)];
    __syncthreads();
    {
        int b = tid >> 4, d = tid & 15;
        float s = 0.f;
#pragma unroll
        for (int c = 0; c < NCH; c++) s += sp[c * 257 + tid];
        sdz[b * 16 + d] = LRC * s * g_Gp[b * D1 + d1_0 + d];
    }
    __syncthreads();

    int col = tid * 4;
    float4 kk[16];
#pragma unroll
    for (int b = 0; b < 16; b++) kk[b] = *(const float4*)(g_K + b * DKK + col);

#pragma unroll 2
    for (int r = 0; r < 16; r++) {
        int d1 = d1_0 + r;
        float4 w4 = __ldg((const float4*)(W0 + (size_t)d1 * DKK + col));
#pragma unroll
        for (int b = 0; b < 16; b++) {
            float s = sdz[b * 16 + r];
            float4 o;
            o.x = w4.x - s * kk[b].x;
            o.y = w4.y - s * kk[b].y;
            o.z = w4.z - s * kk[b].z;
            o.w = w4.w - s * kk[b].w;
            __stcs((float4*)(out_w0 + ((size_t)b * D1 + d1) * DKK + col), o);
        }
    }
}

extern "C" void kernel_launch(void* const* d_in, const int* in_sizes, int n_in,
                              void* d_out, int out_size) {
    const float* x  = (const float*)d_in[0];
    const float* Wk = (const float*)d_in[1];
    const float* Wv = (const float*)d_in[2];
    const float* Wo = (const float*)d_in[3];
    const float* W0 = (const float*)d_in[4];
    const float* W1 = (const float*)d_in[5];

    float* out    = (float*)d_out;
    float* out_w0 = out + (size_t)B * IN;
    float* out_w1 = out_w0 + (size_t)B * D1 * DKK;

    proj_kernel        <<<128, 256>>>(x, Wk, Wv);
    zgelu_kernel       <<<256, 256>>>(W0);
    hdh_kernel         <<<128, 256>>>(W1);
    fused_w1_out_kernel<<<320, 128>>>(W1, Wo, out_w1, out);
    fused_w0_kernel    <<<256, 256>>>(W0, out_w0);
}

// round 6
// speedup vs baseline: 2.8730x; 1.0279x over previous
#include <cuda_runtime.h>
#include <math.h>

#define B    16
#define IN   1024
#define HH   1024
#define DKK  1024
#define D1   4096
#define LRC  0.01f
#define NCH  64
#define CI   16

// ---------------- scratch (allocation-free) ----------------
__device__ __align__(16) float g_K  [B * DKK];          // b-major
__device__ __align__(16) float g_V  [B * HH];           // b-major
__device__ __align__(16) float g_G  [B * D1];           // b-major
__device__ __align__(16) float g_Gp [B * D1];           // b-major
__device__ __align__(16) float g_Hd [B * HH];           // b-major
__device__ __align__(16) float g_dHt[HH * B];           // i-major
__device__ __align__(16) float g_part[NCH * B * D1];    // [c][b][j], 16 MB

__device__ __forceinline__ float warp_sum(float v) {
    v += __shfl_xor_sync(0xffffffffu, v, 16);
    v += __shfl_xor_sync(0xffffffffu, v, 8);
    v += __shfl_xor_sync(0xffffffffu, v, 4);
    v += __shfl_xor_sync(0xffffffffu, v, 2);
    v += __shfl_xor_sync(0xffffffffu, v, 1);
    return v;
}
__device__ __forceinline__ float dot4(float4 a, float4 b) {
    return a.x * b.x + a.y * b.y + a.z * b.z + a.w * b.w;
}

// ---------------- proj: rows 0..1023 -> K, 1024..2047 -> V ----------------
__global__ void proj_kernel(const float* __restrict__ X,
                            const float* __restrict__ Wk,
                            const float* __restrict__ Wv) {
    __shared__ float sm[4][2][64];
    int w = threadIdx.x >> 5, lane = threadIdx.x & 31;
    int rgl = w >> 1, half = w & 1;
    int rg = blockIdx.x * 4 + rgl;            // 0..511
    const float* Wb = (rg >> 8) ? Wv : Wk;
    int row0 = (rg * 4) & 1023;
    int ibase = half * 512;
    const float* wp = Wb + (size_t)row0 * IN + ibase;
    const float* xp = X + ibase;

    float acc[4][16];
#pragma unroll
    for (int r = 0; r < 4; r++)
#pragma unroll
        for (int b = 0; b < 16; b++) acc[r][b] = 0.f;

#pragma unroll
    for (int it = 0; it < 4; it++) {
        int i = it * 128 + lane * 4;
        float4 wv[4];
#pragma unroll
        for (int r = 0; r < 4; r++) wv[r] = __ldg((const float4*)(wp + r * IN + i));
#pragma unroll
        for (int b = 0; b < 16; b++) {
            float4 x4 = __ldg((const float4*)(xp + b * IN + i));
#pragma unroll
            for (int r = 0; r < 4; r++) acc[r][b] += dot4(wv[r], x4);
        }
    }
#pragma unroll
    for (int r = 0; r < 4; r++)
#pragma unroll
        for (int b = 0; b < 16; b++) acc[r][b] = warp_sum(acc[r][b]);
    if (lane == 0) {
#pragma unroll
        for (int r = 0; r < 4; r++)
#pragma unroll
            for (int b = 0; b < 16; b++) sm[rgl][half][r * 16 + b] = acc[r][b];
    }
    __syncthreads();
    {
        int t = threadIdx.x;
        int rg2 = t >> 6, r = (t >> 4) & 3, b = t & 15;
        float v = sm[rg2][0][r * 16 + b] + sm[rg2][1][r * 16 + b];
        int row = (blockIdx.x * 4 + rg2) * 4 + r;
        float* o = (row >> 10) ? g_V : g_K;
        o[b * 1024 + (row & 1023)] = v;
    }
}

// ---------------- zgelu: Z = K @ W0^T ; G, Gp ----------------
__global__ void zgelu_kernel(const float* __restrict__ W0) {
    __shared__ float sm[4][2][64];
    int w = threadIdx.x >> 5, lane = threadIdx.x & 31;
    int rgl = w >> 1, half = w & 1;
    int rg = blockIdx.x * 4 + rgl;            // 0..1023
    int j0 = rg * 4;
    int ibase = half * 512;
    const float* wp = W0 + (size_t)j0 * DKK + ibase;

    float acc[4][16];
#pragma unroll
    for (int r = 0; r < 4; r++)
#pragma unroll
        for (int b = 0; b < 16; b++) acc[r][b] = 0.f;

#pragma unroll
    for (int it = 0; it < 4; it++) {
        int i = it * 128 + lane * 4;
        float4 wv[4];
#pragma unroll
        for (int r = 0; r < 4; r++) wv[r] = __ldg((const float4*)(wp + r * DKK + i));
#pragma unroll
        for (int b = 0; b < 16; b++) {
            float4 k4 = *(const float4*)(g_K + b * DKK + ibase + i);
#pragma unroll
            for (int r = 0; r < 4; r++) acc[r][b] += dot4(wv[r], k4);
        }
    }
#pragma unroll
    for (int r = 0; r < 4; r++)
#pragma unroll
        for (int b = 0; b < 16; b++) acc[r][b] = warp_sum(acc[r][b]);
    if (lane == 0) {
#pragma unroll
        for (int r = 0; r < 4; r++)
#pragma unroll
            for (int b = 0; b < 16; b++) sm[rgl][half][r * 16 + b] = acc[r][b];
    }
    __syncthreads();
    {
        int t = threadIdx.x;
        int rg2 = t >> 6, r = (t >> 4) & 3, b = t & 15;
        float z = sm[rg2][0][r * 16 + b] + sm[rg2][1][r * 16 + b];
        int j = (blockIdx.x * 4 + rg2) * 4 + r;
        float c  = 0.5f * (1.f + erff(z * 0.70710678118654752f));
        float g  = z * c;
        float gp = c + z * 0.39894228040143268f * expf(-0.5f * z * z);
        g_G [b * D1 + j] = g;
        g_Gp[b * D1 + j] = gp;
    }
}

// ---------------- hdh: Hd = G @ W1^T ; dH ----------------
__global__ void hdh_kernel(const float* __restrict__ W1) {
    __shared__ float sm[2][4][64];
    int w = threadIdx.x >> 5, lane = threadIdx.x & 31;
    int rgl = w >> 2, s = w & 3;
    int rg = blockIdx.x * 2 + rgl;            // 0..255
    int i0 = rg * 4;
    int jbase = s * 1024;
    const float* wp = W1 + (size_t)i0 * D1 + jbase;

    float acc[4][16];
#pragma unroll
    for (int r = 0; r < 4; r++)
#pragma unroll
        for (int b = 0; b < 16; b++) acc[r][b] = 0.f;

#pragma unroll
    for (int it = 0; it < 8; it++) {
        int j = it * 128 + lane * 4;
        float4 wv[4];
#pragma unroll
        for (int r = 0; r < 4; r++) wv[r] = __ldg((const float4*)(wp + r * D1 + j));
#pragma unroll
        for (int b = 0; b < 16; b++) {
            float4 g4 = *(const float4*)(g_G + b * D1 + jbase + j);
#pragma unroll
            for (int r = 0; r < 4; r++) acc[r][b] += dot4(wv[r], g4);
        }
    }
#pragma unroll
    for (int r = 0; r < 4; r++)
#pragma unroll
        for (int b = 0; b < 16; b++) acc[r][b] = warp_sum(acc[r][b]);
    if (lane == 0) {
#pragma unroll
        for (int r = 0; r < 4; r++)
#pragma unroll
            for (int b = 0; b < 16; b++) sm[rgl][s][r * 16 + b] = acc[r][b];
    }
    __syncthreads();
    if (threadIdx.x < 128) {
        int t = threadIdx.x;
        int rg2 = t >> 6, r = (t >> 4) & 3, b = t & 15;
        float h = sm[rg2][0][r * 16 + b] + sm[rg2][1][r * 16 + b]
                + sm[rg2][2][r * 16 + b] + sm[rg2][3][r * 16 + b];
        int i = (blockIdx.x * 2 + rg2) * 4 + r;
        g_Hd [b * HH + i] = h;
        g_dHt[i * B + b]  = (h - g_V[b * HH + i]) * (1.0f / (float)HH);
    }
}

// ---------------- MEGA: W1 update + dG partials (blocks 0..255) | output GEMV (256..511) ----------------
// 256 threads per block (the R4 geometry that measured 5086 GB/s).
__global__ void fused_w1_out_kernel(const float* __restrict__ W1,
                                    const float* __restrict__ Wo,
                                    float* __restrict__ out_w1,
                                    float* __restrict__ out) {
    int tid = threadIdx.x;
    if (blockIdx.x < 256) {
        __shared__ float sdh[CI * B];
        int c  = blockIdx.x >> 2;           // 0..63
        int jt = blockIdx.x & 3;
        int i0 = c * CI;
        int j  = jt * 1024 + tid * 4;

        sdh[tid] = g_dHt[i0 * B + tid];     // 16 rows x 16 b
        __syncthreads();

#pragma unroll
        for (int half = 0; half < 2; half++) {
            float4 gg[8], acc[8];
#pragma unroll
            for (int bb = 0; bb < 8; bb++) {
                gg[bb]  = *(const float4*)(g_G + (half * 8 + bb) * D1 + j);
                acc[bb] = make_float4(0.f, 0.f, 0.f, 0.f);
            }
#pragma unroll 4
            for (int r = 0; r < CI; r++) {
                int i = i0 + r;
                float4 w4 = __ldg((const float4*)(W1 + (size_t)i * D1 + j));
                float* dst = out_w1 + (size_t)i * D1 + j;
#pragma unroll
                for (int bb = 0; bb < 8; bb++) {
                    int b = half * 8 + bb;
                    float dh = sdh[r * B + b];
                    acc[bb].x += dh * w4.x;
                    acc[bb].y += dh * w4.y;
                    acc[bb].z += dh * w4.z;
                    acc[bb].w += dh * w4.w;
                    float t = LRC * dh;
                    float4 o;
                    o.x = w4.x - t * gg[bb].x;
                    o.y = w4.y - t * gg[bb].y;
                    o.z = w4.z - t * gg[bb].z;
                    o.w = w4.w - t * gg[bb].w;
                    __stcs((float4*)(dst + (size_t)b * HH * D1), o);
                }
            }
#pragma unroll
            for (int bb = 0; bb < 8; bb++)
                *(float4*)(g_part + ((size_t)c * B + half * 8 + bb) * D1 + j) = acc[bb];
        }
    } else {
        // output = Hd @ Wo^T (split-2, 4 rows/block)
        __shared__ float sm[4][2][B];
        int bx2  = blockIdx.x - 256;
        int w    = tid >> 5;
        int lane = tid & 31;
        int r = w >> 1;
        int s = w & 1;
        int n = bx2 * 4 + r;
        const float* wrow = Wo + (size_t)n * HH + s * 512;

        float acc[B];
#pragma unroll
        for (int b = 0; b < B; b++) acc[b] = 0.f;

#pragma unroll 4
        for (int it = 0; it < 4; it++) {
            int h0 = it * 128 + lane * 4;
            float4 w4 = __ldg((const float4*)(wrow + h0));
#pragma unroll
            for (int b = 0; b < B; b++) {
                float4 h4 = *(const float4*)(g_Hd + b * HH + s * 512 + h0);
                acc[b] += dot4(w4, h4);
            }
        }
#pragma unroll
        for (int b = 0; b < B; b++) acc[b] = warp_sum(acc[b]);
        if (lane == 0) {
#pragma unroll
            for (int b = 0; b < B; b++) sm[r][s][b] = acc[b];
        }
        __syncthreads();
        if (tid < 64) {
            int rr = tid >> 4;
            int b  = tid & 15;
            int nn = bx2 * 4 + rr;
            out[b * IN + nn] = sm[rr][0][b] + sm[rr][1][b];
        }
    }
}

// ---------------- fused: dZ reduce + W0 update. 256 blocks x 256 thr, 16 d1-rows each ----------------
__global__ void fused_w0_kernel(const float* __restrict__ W0,
                                float* __restrict__ out_w0) {
    __shared__ float sdz[256];                 // [b][r]
    int tid  = threadIdx.x;
    int d1_0 = blockIdx.x * 16;

    {
        int b = tid >> 4, d = tid & 15;
        const float* pp = g_part + (size_t)b * D1 + d1_0 + d;
        float s = 0.f;
#pragma unroll 16
        for (int c = 0; c < NCH; c++)
            s += pp[(size_t)c * (B * D1)];
        sdz[b * 16 + d] = LRC * s * g_Gp[b * D1 + d1_0 + d];
    }
    __syncthreads();

    int col = tid * 4;
    float4 kk[16];
#pragma unroll
    for (int b = 0; b < 16; b++) kk[b] = *(const float4*)(g_K + b * DKK + col);

#pragma unroll 2
    for (int r = 0; r < 16; r++) {
        int d1 = d1_0 + r;
        float4 w4 = __ldg((const float4*)(W0 + (size_t)d1 * DKK + col));
#pragma unroll
        for (int b = 0; b < 16; b++) {
            float s = sdz[b * 16 + r];
            float4 o;
            o.x = w4.x - s * kk[b].x;
            o.y = w4.y - s * kk[b].y;
            o.z = w4.z - s * kk[b].z;
            o.w = w4.w - s * kk[b].w;
            __stcs((float4*)(out_w0 + ((size_t)b * D1 + d1) * DKK + col), o);
        }
    }
}

extern "C" void kernel_launch(void* const* d_in, const int* in_sizes, int n_in,
                              void* d_out, int out_size) {
    const float* x  = (const float*)d_in[0];
    const float* Wk = (const float*)d_in[1];
    const float* Wv = (const float*)d_in[2];
    const float* Wo = (const float*)d_in[3];
    const float* W0 = (const float*)d_in[4];
    const float* W1 = (const float*)d_in[5];

    float* out    = (float*)d_out;
    float* out_w0 = out + (size_t)B * IN;
    float* out_w1 = out_w0 + (size_t)B * D1 * DKK;

    proj_kernel        <<<128, 256>>>(x, Wk, Wv);
    zgelu_kernel       <<<256, 256>>>(W0);
    hdh_kernel         <<<128, 256>>>(W1);
    fused_w1_out_kernel<<<512, 256>>>(W1, Wo, out_w1, out);
    fused_w0_kernel    <<<256, 256>>>(W0, out_w0);
}